// round 11
// baseline (speedup 1.0000x reference)
#include <cuda_runtime.h>
#include <cstdint>

// Problem dims (fixed for QuantizedLinear_49246095015985)
#define M_DIM 8192
#define K_DIM 4096
#define N_DIM 4096

// GEMM tiling (bf16): 128x128 CTA tile, k-slab = 64 elements (two 8KB blocks)
#define BM 128
#define BN 128
#define BKE 64                  // k elements per pipeline slab
#define NST 3                   // pipeline stages
#define NIT (K_DIM / BKE)       // 64 k-slabs

#define BLK 8192                // bytes per 32-element sub-block (128 rows x 64B)
#define SLAB (2 * BLK)          // 16 KB per matrix per stage
#define SLAB_W 2048             // words per 8KB sub-block
#define OFF_A 0
#define OFF_B (NST * SLAB)                   // 49152
#define OFF_EPI (OFF_B + NST * SLAB)         // 98304
#define OFF_MB (OFF_EPI + 1024)              // 3 x 8B full barriers
#define SMEM_BYTES (OFF_MB + 64 + 1024)

// Scratch (device globals: allocation-free rule).
// TILED + PRE-SWIZZLED bf16 layouts (UNCHANGED from round 10):
//   g_Ab = [64 mtiles][128 k32-blocks][8KB block]  (centered activations)
//   g_Wb = [32 ntiles][128 k32-blocks][8KB block]  (centered weights)
__device__ uint32_t g_Ab[(size_t)M_DIM * K_DIM / 2];   // 64 MB
__device__ uint32_t g_Wb[(size_t)N_DIM * K_DIM / 2];   // 32 MB

// ---------------------------------------------------------------------------
// Helpers
// ---------------------------------------------------------------------------
__device__ __forceinline__ uint32_t cvta_smem(const void* p) {
    return (uint32_t)__cvta_generic_to_shared(p);
}

// Within an 8KB sub-block: row = 64B (4 x 16B chunks), XOR-swizzled chunk pos.
__device__ __forceinline__ uint32_t swz(int row, int chunk) {
    return (uint32_t)(row * 64 + ((chunk ^ ((row >> 1) & 3)) << 4));
}

#define MBAR_INIT(addr, cnt) \
    asm volatile("mbarrier.init.shared.b64 [%0], %1;" :: "r"(addr), "r"(cnt) : "memory")

#define MBAR_EXPECT_TX(addr, bytes) \
    asm volatile("mbarrier.arrive.expect_tx.shared.b64 _, [%0], %1;" \
                 :: "r"(addr), "r"(bytes) : "memory")

#define MB_WAIT(addr, ph) do { \
    uint32_t _d_; \
    asm volatile("{\n\t.reg .pred p;\n\t" \
        "mbarrier.try_wait.parity.acquire.cta.shared::cta.b64 p, [%1], %2;\n\t" \
        "selp.b32 %0, 1, 0, p;\n\t}" : "=r"(_d_) : "r"(addr), "r"(ph) : "memory"); \
    while (!_d_) { \
        asm volatile("{\n\t.reg .pred p;\n\t" \
            "mbarrier.try_wait.parity.acquire.cta.shared::cta.b64 p, [%1], %2, 0x989680;\n\t" \
            "selp.b32 %0, 1, 0, p;\n\t}" : "=r"(_d_) : "r"(addr), "r"(ph) : "memory"); \
    } \
} while (0)

__device__ __forceinline__ void bulk_cp(uint32_t dst, const void* src,
                                        uint32_t bytes, uint32_t mbar) {
    asm volatile(
        "cp.async.bulk.shared::cluster.global.mbarrier::complete_tx::bytes "
        "[%0], [%1], %2, [%3];"
        :: "r"(dst), "l"(src), "r"(bytes), "r"(mbar) : "memory");
}

__device__ __forceinline__ void ldsm_x4(uint32_t (&r)[4], uint32_t addr) {
    asm volatile("ldmatrix.sync.aligned.m8n8.x4.shared.b16 {%0,%1,%2,%3}, [%4];"
                 : "=r"(r[0]), "=r"(r[1]), "=r"(r[2]), "=r"(r[3]) : "r"(addr));
}

__device__ __forceinline__ void mma_bf16(float (&c)[4], const uint32_t (&a)[4],
                                         uint32_t b0, uint32_t b1) {
    asm volatile(
        "mma.sync.aligned.m16n8k16.row.col.f32.bf16.bf16.f32 "
        "{%0,%1,%2,%3}, {%4,%5,%6,%7}, {%8,%9}, {%0,%1,%2,%3};"
        : "+f"(c[0]), "+f"(c[1]), "+f"(c[2]), "+f"(c[3])
        : "r"(a[0]), "r"(a[1]), "r"(a[2]), "r"(a[3]), "r"(b0), "r"(b1));
}

// pack two floats into bf16x2 word: low half = lo, high half = hi
__device__ __forceinline__ uint32_t pack_bf16x2(float lo, float hi) {
    uint32_t r;
    asm("cvt.rn.bf16x2.f32 %0, %1, %2;" : "=r"(r) : "f"(hi), "f"(lo));
    return r;
}

// ---------------------------------------------------------------------------
// Kernel 1: quantize + center activations -> bf16, tiled+swizzled layout.
// ---------------------------------------------------------------------------
__global__ void quant_x_kernel(const float* __restrict__ x,
                               const float* __restrict__ act_scale,
                               const int* __restrict__ act_zp)
{
    const int row = blockIdx.x;
    const int mtile = row >> 7, r = row & 127;
    const float s   = act_scale[0];
    const float zpf = (float)act_zp[0];
    const int tid = threadIdx.x;

    const int kblk = tid >> 1;              // 0..127 (32-element blocks)
    const int g0 = (tid & 1) << 1;          // chunk pair within block: 0 or 2
    const float4* xr = reinterpret_cast<const float4*>(
        x + (size_t)row * K_DIM + kblk * 32 + g0 * 8);

    size_t base = ((size_t)(mtile * 128 + kblk)) * SLAB_W;
    #pragma unroll
    for (int c = 0; c < 2; ++c) {           // two 16B chunks (8 bf16 each)
        float4 v0 = xr[c * 2 + 0];
        float4 v1 = xr[c * 2 + 1];
        float q[8] = {v0.x, v0.y, v0.z, v0.w, v1.x, v1.y, v1.z, v1.w};
        #pragma unroll
        for (int e = 0; e < 8; ++e)
            q[e] = fminf(fmaxf(rintf(__fdiv_rn(q[e], s)) + zpf, 0.f), 255.f) - zpf;
        uint4 w;
        w.x = pack_bf16x2(q[0], q[1]);
        w.y = pack_bf16x2(q[2], q[3]);
        w.z = pack_bf16x2(q[4], q[5]);
        w.w = pack_bf16x2(q[6], q[7]);
        int chunk = g0 + c;
        uint32_t woff = (uint32_t)(r * 16 + ((chunk ^ ((r >> 1) & 3)) << 2));
        *reinterpret_cast<uint4*>(&g_Ab[base + woff]) = w;
    }
}

// ---------------------------------------------------------------------------
// Kernel 2: center weights -> bf16, tiled+swizzled layout.
// ---------------------------------------------------------------------------
__global__ void pack_w_kernel(const int* __restrict__ wq,
                              const int* __restrict__ wzp)
{
    const int row = blockIdx.x;
    const int ntile = row >> 7, r = row & 127;
    const float zw = (float)wzp[row];
    const int tid = threadIdx.x;

    const int kblk = tid >> 1;
    const int g0 = (tid & 1) << 1;
    const int4* wr = reinterpret_cast<const int4*>(
        wq + (size_t)row * K_DIM + kblk * 32 + g0 * 8);

    size_t base = ((size_t)(ntile * 128 + kblk)) * SLAB_W;
    #pragma unroll
    for (int c = 0; c < 2; ++c) {
        int4 v0 = wr[c * 2 + 0];
        int4 v1 = wr[c * 2 + 1];
        float q[8] = {(float)v0.x, (float)v0.y, (float)v0.z, (float)v0.w,
                      (float)v1.x, (float)v1.y, (float)v1.z, (float)v1.w};
        #pragma unroll
        for (int e = 0; e < 8; ++e) q[e] -= zw;
        uint4 w;
        w.x = pack_bf16x2(q[0], q[1]);
        w.y = pack_bf16x2(q[2], q[3]);
        w.z = pack_bf16x2(q[4], q[5]);
        w.w = pack_bf16x2(q[6], q[7]);
        int chunk = g0 + c;
        uint32_t woff = (uint32_t)(r * 16 + ((chunk ^ ((r >> 1) & 3)) << 2));
        *reinterpret_cast<uint4*>(&g_Wb[base + woff]) = w;
    }
}

// ---------------------------------------------------------------------------
// Kernel 3: bf16 HMMA GEMM, 128x128 CTA tile, 8 warps (4x2), warp tile 32x64.
// 3-stage ring, 16KB bulk copies per matrix per stage (= 2 k32 sub-blocks).
// ---------------------------------------------------------------------------
__global__ __launch_bounds__(256, 2)
void gemm_hmma_kernel(const float* __restrict__ wscale,
                      const float* __restrict__ ascale,
                      const float* __restrict__ bias,
                      float*       __restrict__ out)
{
    extern __shared__ __align__(1024) uint8_t smem_raw[];
    uint32_t raw = cvta_smem(smem_raw);
    uint32_t sbase = (raw + 1023u) & ~1023u;
    uint8_t* smem_gen = smem_raw + (sbase - raw);

    const int tid = threadIdx.x;
    const int wid = tid >> 5;
    const int lid = tid & 31;
    const int wm  = wid & 3;        // warp row (32 rows each)
    const int wn  = wid >> 2;       // warp col (64 cols each)
    const int tile_m = blockIdx.y << 7;
    const int tile_n = blockIdx.x << 7;

    const uint8_t* Abase = reinterpret_cast<const uint8_t*>(g_Ab)
                         + (size_t)blockIdx.y * 128 * BLK;
    const uint8_t* Bbase = reinterpret_cast<const uint8_t*>(g_Wb)
                         + (size_t)blockIdx.x * 128 * BLK;
    const uint32_t mbf = sbase + OFF_MB;

    if (tid == 0) {
        #pragma unroll
        for (int s = 0; s < NST; ++s) MBAR_INIT(mbf + s * 8, 1);
        asm volatile("fence.proxy.async.shared::cta;" ::: "memory");
    }

    // Epilogue constants
    float* tsc = reinterpret_cast<float*>(smem_gen + OFF_EPI);
    float* tbs = reinterpret_cast<float*>(smem_gen + OFF_EPI + 512);
    if (tid >= 128) {
        const float sa = ascale[0];
        int n = tid - 128;
        int o = tile_n + n;
        tsc[n] = sa * wscale[o];
        tbs[n] = bias[o];
    }
    __syncthreads();

    // Prologue: fill NST-1 stages
    if (tid == 0) {
        #pragma unroll
        for (int s = 0; s < NST - 1; ++s) {
            MBAR_EXPECT_TX(mbf + s * 8, 2 * SLAB);
            bulk_cp(sbase + OFF_A + s * SLAB, Abase + (size_t)s * SLAB, SLAB, mbf + s * 8);
            bulk_cp(sbase + OFF_B + s * SLAB, Bbase + (size_t)s * SLAB, SLAB, mbf + s * 8);
        }
    }

    float acc[2][8][4];
    #pragma unroll
    for (int mt = 0; mt < 2; ++mt)
        #pragma unroll
        for (int nt = 0; nt < 8; ++nt)
            #pragma unroll
            for (int q = 0; q < 4; ++q) acc[mt][nt][q] = 0.f;

    // ldmatrix lane geometry (chunk = 16B = 8 bf16 = k8)
    const int a_row = (lid & 7) + ((lid >> 3) & 1) * 8;
    const int a_ch  = (lid >> 4);
    const int b_row = (lid & 7) + (lid >> 4) * 8;
    const int b_ch  = ((lid >> 3) & 1);

    int pf[NST] = {0, 0, 0};

    for (int it = 0; it < NIT; ++it) {
        int buf = it % NST;
        MB_WAIT(mbf + buf * 8, pf[buf]); pf[buf] ^= 1;

        uint32_t aS = sbase + OFF_A + buf * SLAB;
        uint32_t bS = sbase + OFF_B + buf * SLAB;

        #pragma unroll
        for (int ks = 0; ks < 4; ++ks) {           // four k16 steps per slab
            const uint32_t aSub = aS + (ks >> 1) * BLK;
            const uint32_t bSub = bS + (ks >> 1) * BLK;
            const int cb = (ks & 1) << 1;
            uint32_t a[2][4];
            #pragma unroll
            for (int mt = 0; mt < 2; ++mt)
                ldsm_x4(a[mt], aSub + swz(wm * 32 + mt * 16 + a_row, cb + a_ch));
            uint32_t b[8][2];
            #pragma unroll
            for (int b4 = 0; b4 < 4; ++b4) {
                uint32_t r4[4];
                ldsm_x4(r4, bSub + swz(wn * 64 + b4 * 16 + b_row, cb + b_ch));
                b[2*b4][0] = r4[0]; b[2*b4][1] = r4[1];
                b[2*b4+1][0] = r4[2]; b[2*b4+1][1] = r4[3];
            }
            #pragma unroll
            for (int mt = 0; mt < 2; ++mt)
                #pragma unroll
                for (int nt = 0; nt < 8; ++nt)
                    mma_bf16(acc[mt][nt], a[mt], b[nt][0], b[nt][1]);
        }

        __syncthreads();
        int nx = it + NST - 1;
        if (tid == 0 && nx < NIT) {
            int s = nx % NST;
            MBAR_EXPECT_TX(mbf + s * 8, 2 * SLAB);
            bulk_cp(sbase + OFF_A + s * SLAB, Abase + (size_t)nx * SLAB, SLAB, mbf + s * 8);
            bulk_cp(sbase + OFF_B + s * SLAB, Bbase + (size_t)nx * SLAB, SLAB, mbf + s * 8);
        }
    }

    // ---------------- Epilogue: out = tsc[n]*acc + tbs[n] -------------------
    const int qrow = lid >> 2;
    const int qcol = (lid & 3) << 1;
    #pragma unroll
    for (int mt = 0; mt < 2; ++mt) {
        const int ml0 = wm * 32 + mt * 16 + qrow;
        float* orow0 = out + (size_t)(tile_m + ml0) * N_DIM + tile_n;
        float* orow1 = orow0 + (size_t)8 * N_DIM;
        #pragma unroll
        for (int nt = 0; nt < 8; ++nt) {
            const int nl = wn * 64 + nt * 8 + qcol;
            const float s0 = tsc[nl], s1 = tsc[nl + 1];
            const float g0 = tbs[nl], g1 = tbs[nl + 1];
            float2 v0, v1;
            v0.x = s0 * acc[mt][nt][0] + g0;
            v0.y = s1 * acc[mt][nt][1] + g1;
            v1.x = s0 * acc[mt][nt][2] + g0;
            v1.y = s1 * acc[mt][nt][3] + g1;
            *reinterpret_cast<float2*>(orow0 + nl) = v0;
            *reinterpret_cast<float2*>(orow1 + nl) = v1;
        }
    }
}

// ---------------------------------------------------------------------------
// Launch
// ---------------------------------------------------------------------------
extern "C" void kernel_launch(void* const* d_in, const int* in_sizes, int n_in,
                              void* d_out, int out_size)
{
    const float* x       = (const float*)d_in[0];
    const int*   wq      = (const int*)  d_in[1];
    const float* wscale  = (const float*)d_in[2];
    const int*   wzp     = (const int*)  d_in[3];
    const float* ascale  = (const float*)d_in[4];
    const int*   azp     = (const int*)  d_in[5];
    const float* bias    = (const float*)d_in[6];
    float*       out     = (float*)d_out;

    cudaFuncSetAttribute(gemm_hmma_kernel,
                         cudaFuncAttributeMaxDynamicSharedMemorySize, SMEM_BYTES);

    quant_x_kernel<<<M_DIM, 256>>>(x, ascale, azp);
    pack_w_kernel<<<N_DIM, 256>>>(wq, wzp);

    dim3 grid(N_DIM / BN, M_DIM / BM);   // (32, 64)
    gemm_hmma_kernel<<<grid, 256, SMEM_BYTES>>>(wscale, ascale, bias, out);
}

// round 12
// speedup vs baseline: 1.5667x; 1.5667x over previous
#include <cuda_runtime.h>
#include <cstdint>

// Problem dims (fixed for QuantizedLinear_49246095015985)
#define M_DIM 8192
#define K_DIM 4096
#define N_DIM 4096

// GEMM tiling (bf16): 128x128 CTA tile, k-slab = 32 elements (ROUND-10 CONFIG)
#define BM 128
#define BN 128
#define BKE 32                  // k elements per slab
#define NST 4                   // pipeline stages
#define NIT (K_DIM / BKE)       // 128 k-slabs

#define SLAB 8192               // 128 rows x 64B, per matrix per stage
#define SLAB_W 2048             // words per slab
#define OFF_A 0
#define OFF_B (NST * SLAB)                   // 32768
#define OFF_EPI (OFF_B + NST * SLAB)         // 65536
#define OFF_MBF (OFF_EPI + 1024)             // 4 x 8B full barriers (tx)
#define OFF_MBE (OFF_MBF + 32)               // 4 x 8B empty barriers (count 256)
#define SMEM_BYTES (OFF_MBE + 32 + 1024)

// Scratch (device globals: allocation-free rule).
// TILED + PRE-SWIZZLED bf16 layouts (UNCHANGED):
//   g_Ab = [64 mtiles][128 k32-blocks][8KB block]  (centered activations)
//   g_Wb = [32 ntiles][128 k32-blocks][8KB block]  (centered weights)
__device__ uint32_t g_Ab[(size_t)M_DIM * K_DIM / 2];   // 64 MB
__device__ uint32_t g_Wb[(size_t)N_DIM * K_DIM / 2];   // 32 MB

// ---------------------------------------------------------------------------
// Helpers
// ---------------------------------------------------------------------------
__device__ __forceinline__ uint32_t cvta_smem(const void* p) {
    return (uint32_t)__cvta_generic_to_shared(p);
}

// Within an 8KB block: row = 64B (4 x 16B chunks), XOR-swizzled chunk position.
__device__ __forceinline__ uint32_t swz(int row, int chunk) {
    return (uint32_t)(row * 64 + ((chunk ^ ((row >> 1) & 3)) << 4));
}

#define MBAR_INIT(addr, cnt) \
    asm volatile("mbarrier.init.shared.b64 [%0], %1;" :: "r"(addr), "r"(cnt) : "memory")

#define MBAR_EXPECT_TX(addr, bytes) \
    asm volatile("mbarrier.arrive.expect_tx.shared.b64 _, [%0], %1;" \
                 :: "r"(addr), "r"(bytes) : "memory")

#define MBAR_ARRIVE(addr) \
    asm volatile("mbarrier.arrive.shared.b64 _, [%0];" :: "r"(addr) : "memory")

#define MB_WAIT(addr, ph) do { \
    uint32_t _d_; \
    asm volatile("{\n\t.reg .pred p;\n\t" \
        "mbarrier.try_wait.parity.acquire.cta.shared::cta.b64 p, [%1], %2;\n\t" \
        "selp.b32 %0, 1, 0, p;\n\t}" : "=r"(_d_) : "r"(addr), "r"(ph) : "memory"); \
    while (!_d_) { \
        asm volatile("{\n\t.reg .pred p;\n\t" \
            "mbarrier.try_wait.parity.acquire.cta.shared::cta.b64 p, [%1], %2, 0x989680;\n\t" \
            "selp.b32 %0, 1, 0, p;\n\t}" : "=r"(_d_) : "r"(addr), "r"(ph) : "memory"); \
    } \
} while (0)

__device__ __forceinline__ void bulk_cp(uint32_t dst, const void* src,
                                        uint32_t bytes, uint32_t mbar) {
    asm volatile(
        "cp.async.bulk.shared::cluster.global.mbarrier::complete_tx::bytes "
        "[%0], [%1], %2, [%3];"
        :: "r"(dst), "l"(src), "r"(bytes), "r"(mbar) : "memory");
}

__device__ __forceinline__ void ldsm_x4(uint32_t (&r)[4], uint32_t addr) {
    asm volatile("ldmatrix.sync.aligned.m8n8.x4.shared.b16 {%0,%1,%2,%3}, [%4];"
                 : "=r"(r[0]), "=r"(r[1]), "=r"(r[2]), "=r"(r[3]) : "r"(addr));
}

__device__ __forceinline__ void mma_bf16(float (&c)[4], const uint32_t (&a)[4],
                                         uint32_t b0, uint32_t b1) {
    asm volatile(
        "mma.sync.aligned.m16n8k16.row.col.f32.bf16.bf16.f32 "
        "{%0,%1,%2,%3}, {%4,%5,%6,%7}, {%8,%9}, {%0,%1,%2,%3};"
        : "+f"(c[0]), "+f"(c[1]), "+f"(c[2]), "+f"(c[3])
        : "r"(a[0]), "r"(a[1]), "r"(a[2]), "r"(a[3]), "r"(b0), "r"(b1));
}

// pack two floats into bf16x2 word: low half = lo, high half = hi
__device__ __forceinline__ uint32_t pack_bf16x2(float lo, float hi) {
    uint32_t r;
    asm("cvt.rn.bf16x2.f32 %0, %1, %2;" : "=r"(r) : "f"(hi), "f"(lo));
    return r;
}

// ---------------------------------------------------------------------------
// Kernel 1: quantize + center activations -> bf16, tiled+swizzled layout.
// ---------------------------------------------------------------------------
__global__ void quant_x_kernel(const float* __restrict__ x,
                               const float* __restrict__ act_scale,
                               const int* __restrict__ act_zp)
{
    const int row = blockIdx.x;
    const int mtile = row >> 7, r = row & 127;
    const float s   = act_scale[0];
    const float zpf = (float)act_zp[0];
    const int tid = threadIdx.x;

    const int kblk = tid >> 1;              // 0..127 (32-element blocks)
    const int g0 = (tid & 1) << 1;          // chunk pair within block: 0 or 2
    const float4* xr = reinterpret_cast<const float4*>(
        x + (size_t)row * K_DIM + kblk * 32 + g0 * 8);

    size_t base = ((size_t)(mtile * 128 + kblk)) * SLAB_W;
    #pragma unroll
    for (int c = 0; c < 2; ++c) {           // two 16B chunks (8 bf16 each)
        float4 v0 = xr[c * 2 + 0];
        float4 v1 = xr[c * 2 + 1];
        float q[8] = {v0.x, v0.y, v0.z, v0.w, v1.x, v1.y, v1.z, v1.w};
        #pragma unroll
        for (int e = 0; e < 8; ++e)
            q[e] = fminf(fmaxf(rintf(__fdiv_rn(q[e], s)) + zpf, 0.f), 255.f) - zpf;
        uint4 w;
        w.x = pack_bf16x2(q[0], q[1]);
        w.y = pack_bf16x2(q[2], q[3]);
        w.z = pack_bf16x2(q[4], q[5]);
        w.w = pack_bf16x2(q[6], q[7]);
        int chunk = g0 + c;
        uint32_t woff = (uint32_t)(r * 16 + ((chunk ^ ((r >> 1) & 3)) << 2));
        *reinterpret_cast<uint4*>(&g_Ab[base + woff]) = w;
    }
}

// ---------------------------------------------------------------------------
// Kernel 2: center weights -> bf16, tiled+swizzled layout.
// ---------------------------------------------------------------------------
__global__ void pack_w_kernel(const int* __restrict__ wq,
                              const int* __restrict__ wzp)
{
    const int row = blockIdx.x;
    const int ntile = row >> 7, r = row & 127;
    const float zw = (float)wzp[row];
    const int tid = threadIdx.x;

    const int kblk = tid >> 1;
    const int g0 = (tid & 1) << 1;
    const int4* wr = reinterpret_cast<const int4*>(
        wq + (size_t)row * K_DIM + kblk * 32 + g0 * 8);

    size_t base = ((size_t)(ntile * 128 + kblk)) * SLAB_W;
    #pragma unroll
    for (int c = 0; c < 2; ++c) {
        int4 v0 = wr[c * 2 + 0];
        int4 v1 = wr[c * 2 + 1];
        float q[8] = {(float)v0.x, (float)v0.y, (float)v0.z, (float)v0.w,
                      (float)v1.x, (float)v1.y, (float)v1.z, (float)v1.w};
        #pragma unroll
        for (int e = 0; e < 8; ++e) q[e] -= zw;
        uint4 w;
        w.x = pack_bf16x2(q[0], q[1]);
        w.y = pack_bf16x2(q[2], q[3]);
        w.z = pack_bf16x2(q[4], q[5]);
        w.w = pack_bf16x2(q[6], q[7]);
        int chunk = g0 + c;
        uint32_t woff = (uint32_t)(r * 16 + ((chunk ^ ((r >> 1) & 3)) << 2));
        *reinterpret_cast<uint4*>(&g_Wb[base + woff]) = w;
    }
}

// ---------------------------------------------------------------------------
// Kernel 3: bf16 HMMA GEMM, 128x128 CTA tile, 8 warps (4x2), warp tile 32x64.
// 4-stage ring, 8KB bulk copies. Mainloop is __syncthreads-FREE:
//   full[s]: tx-barrier (producer expect_tx + TMA complete_tx)
//   empty[s]: arrive-count-256 barrier (all consumers arrive after use)
// Producer = tid 0, waits empty with initial parity 1 (first NST passes free).
// ---------------------------------------------------------------------------
__global__ __launch_bounds__(256, 2)
void gemm_hmma_kernel(const float* __restrict__ wscale,
                      const float* __restrict__ ascale,
                      const float* __restrict__ bias,
                      float*       __restrict__ out)
{
    extern __shared__ __align__(1024) uint8_t smem_raw[];
    uint32_t raw = cvta_smem(smem_raw);
    uint32_t sbase = (raw + 1023u) & ~1023u;
    uint8_t* smem_gen = smem_raw + (sbase - raw);

    const int tid = threadIdx.x;
    const int wid = tid >> 5;
    const int lid = tid & 31;
    const int wm  = wid & 3;        // warp row (32 rows each)
    const int wn  = wid >> 2;       // warp col (64 cols each)
    const int tile_m = blockIdx.y << 7;
    const int tile_n = blockIdx.x << 7;

    const uint8_t* Abase = reinterpret_cast<const uint8_t*>(g_Ab)
                         + (size_t)blockIdx.y * 128 * SLAB;
    const uint8_t* Bbase = reinterpret_cast<const uint8_t*>(g_Wb)
                         + (size_t)blockIdx.x * 128 * SLAB;
    const uint32_t mbf = sbase + OFF_MBF;
    const uint32_t mbe = sbase + OFF_MBE;

    if (tid == 0) {
        #pragma unroll
        for (int s = 0; s < NST; ++s) {
            MBAR_INIT(mbf + s * 8, 1);
            MBAR_INIT(mbe + s * 8, 256);
        }
        asm volatile("fence.proxy.async.shared::cta;" ::: "memory");
    }

    // Epilogue constants
    float* tsc = reinterpret_cast<float*>(smem_gen + OFF_EPI);
    float* tbs = reinterpret_cast<float*>(smem_gen + OFF_EPI + 512);
    if (tid >= 128) {
        const float sa = ascale[0];
        int n = tid - 128;
        int o = tile_n + n;
        tsc[n] = sa * wscale[o];
        tbs[n] = bias[o];
    }
    __syncthreads();   // barriers initialized + constants visible

    // Producer phase state (tid 0 only): initial parity 1 -> first waits pass.
    int pe[NST] = {1, 1, 1, 1};

    // Prologue: fill NST-1 stages
    if (tid == 0) {
        #pragma unroll
        for (int s = 0; s < NST - 1; ++s) {
            MB_WAIT(mbe + s * 8, pe[s]); pe[s] ^= 1;   // passes immediately
            MBAR_EXPECT_TX(mbf + s * 8, 2 * SLAB);
            bulk_cp(sbase + OFF_A + s * SLAB, Abase + (size_t)s * SLAB, SLAB, mbf + s * 8);
            bulk_cp(sbase + OFF_B + s * SLAB, Bbase + (size_t)s * SLAB, SLAB, mbf + s * 8);
        }
    }

    float acc[2][8][4];
    #pragma unroll
    for (int mt = 0; mt < 2; ++mt)
        #pragma unroll
        for (int nt = 0; nt < 8; ++nt)
            #pragma unroll
            for (int q = 0; q < 4; ++q) acc[mt][nt][q] = 0.f;

    // ldmatrix lane geometry (chunk = 16B = 8 bf16 = k8)
    const int a_row = (lid & 7) + ((lid >> 3) & 1) * 8;
    const int a_ch  = (lid >> 4);
    const int b_row = (lid & 7) + (lid >> 4) * 8;
    const int b_ch  = ((lid >> 3) & 1);

    int pf[NST] = {0, 0, 0, 0};

    for (int it = 0; it < NIT; ++it) {
        int buf = it & (NST - 1);
        MB_WAIT(mbf + buf * 8, pf[buf]); pf[buf] ^= 1;

        uint32_t aS = sbase + OFF_A + buf * SLAB;
        uint32_t bS = sbase + OFF_B + buf * SLAB;

        #pragma unroll
        for (int ks = 0; ks < 2; ++ks) {           // two k16 steps per slab
            const int cb = ks << 1;
            uint32_t a[2][4];
            #pragma unroll
            for (int mt = 0; mt < 2; ++mt)
                ldsm_x4(a[mt], aS + swz(wm * 32 + mt * 16 + a_row, cb + a_ch));
            uint32_t b[8][2];
            #pragma unroll
            for (int b4 = 0; b4 < 4; ++b4) {
                uint32_t r4[4];
                ldsm_x4(r4, bS + swz(wn * 64 + b4 * 16 + b_row, cb + b_ch));
                b[2*b4][0] = r4[0]; b[2*b4][1] = r4[1];
                b[2*b4+1][0] = r4[2]; b[2*b4+1][1] = r4[3];
            }
            #pragma unroll
            for (int mt = 0; mt < 2; ++mt)
                #pragma unroll
                for (int nt = 0; nt < 8; ++nt)
                    mma_bf16(acc[mt][nt], a[mt], b[nt][0], b[nt][1]);
        }

        // Done consuming this stage (ldmatrix results are in registers).
        MBAR_ARRIVE(mbe + buf * 8);

        // Producer: refill the ring (slot freed at iteration it-1).
        int nx = it + NST - 1;
        if (tid == 0 && nx < NIT) {
            int s = nx & (NST - 1);
            MB_WAIT(mbe + s * 8, pe[s]); pe[s] ^= 1;   // backpressure
            MBAR_EXPECT_TX(mbf + s * 8, 2 * SLAB);
            bulk_cp(sbase + OFF_A + s * SLAB, Abase + (size_t)nx * SLAB, SLAB, mbf + s * 8);
            bulk_cp(sbase + OFF_B + s * SLAB, Bbase + (size_t)nx * SLAB, SLAB, mbf + s * 8);
        }
    }

    // ---------------- Epilogue: out = tsc[n]*acc + tbs[n] -------------------
    const int qrow = lid >> 2;
    const int qcol = (lid & 3) << 1;
    #pragma unroll
    for (int mt = 0; mt < 2; ++mt) {
        const int ml0 = wm * 32 + mt * 16 + qrow;
        float* orow0 = out + (size_t)(tile_m + ml0) * N_DIM + tile_n;
        float* orow1 = orow0 + (size_t)8 * N_DIM;
        #pragma unroll
        for (int nt = 0; nt < 8; ++nt) {
            const int nl = wn * 64 + nt * 8 + qcol;
            const float s0 = tsc[nl], s1 = tsc[nl + 1];
            const float g0 = tbs[nl], g1 = tbs[nl + 1];
            float2 v0, v1;
            v0.x = s0 * acc[mt][nt][0] + g0;
            v0.y = s1 * acc[mt][nt][1] + g1;
            v1.x = s0 * acc[mt][nt][2] + g0;
            v1.y = s1 * acc[mt][nt][3] + g1;
            *reinterpret_cast<float2*>(orow0 + nl) = v0;
            *reinterpret_cast<float2*>(orow1 + nl) = v1;
        }
    }
}

// ---------------------------------------------------------------------------
// Launch
// ---------------------------------------------------------------------------
extern "C" void kernel_launch(void* const* d_in, const int* in_sizes, int n_in,
                              void* d_out, int out_size)
{
    const float* x       = (const float*)d_in[0];
    const int*   wq      = (const int*)  d_in[1];
    const float* wscale  = (const float*)d_in[2];
    const int*   wzp     = (const int*)  d_in[3];
    const float* ascale  = (const float*)d_in[4];
    const int*   azp     = (const int*)  d_in[5];
    const float* bias    = (const float*)d_in[6];
    float*       out     = (float*)d_out;

    cudaFuncSetAttribute(gemm_hmma_kernel,
                         cudaFuncAttributeMaxDynamicSharedMemorySize, SMEM_BYTES);

    quant_x_kernel<<<M_DIM, 256>>>(x, ascale, azp);
    pack_w_kernel<<<N_DIM, 256>>>(wq, wzp);

    dim3 grid(N_DIM / BN, M_DIM / BM);   // (32, 64)
    gemm_hmma_kernel<<<grid, 256, SMEM_BYTES>>>(wscale, ascale, bias, out);
}

// round 13
// speedup vs baseline: 1.6878x; 1.0773x over previous
#include <cuda_runtime.h>
#include <cstdint>

// Problem dims (fixed for QuantizedLinear_49246095015985)
#define M_DIM 8192
#define K_DIM 4096
#define N_DIM 4096

// GEMM tiling (bf16): 128x128 CTA tile, k-slab = 32 elements
#define BM 128
#define BN 128
#define BKE 32                  // k elements per slab
#define NST 6                   // pipeline stages (deeper ring)
#define NIT (K_DIM / BKE)       // 128 k-slabs

#define SLAB 8192               // 128 rows x 64B, per matrix per stage
#define SLAB_W 2048             // words per slab
#define OFF_A 0
#define OFF_B (NST * SLAB)                   // 49152
#define OFF_EPI (OFF_B + NST * SLAB)         // 98304
#define OFF_MBF (OFF_EPI + 1024)             // 6 x 8B full barriers (tx)
#define OFF_MBE (OFF_MBF + 48)               // 6 x 8B empty barriers (count 256)
#define SMEM_BYTES (OFF_MBE + 48 + 1024)

// Scratch (device globals: allocation-free rule).
// TILED + PRE-SWIZZLED bf16 layouts (UNCHANGED):
//   g_Ab = [64 mtiles][128 k32-blocks][8KB block]  (centered activations)
//   g_Wb = [32 ntiles][128 k32-blocks][8KB block]  (centered weights)
__device__ uint32_t g_Ab[(size_t)M_DIM * K_DIM / 2];   // 64 MB
__device__ uint32_t g_Wb[(size_t)N_DIM * K_DIM / 2];   // 32 MB

// ---------------------------------------------------------------------------
// Helpers
// ---------------------------------------------------------------------------
__device__ __forceinline__ uint32_t cvta_smem(const void* p) {
    return (uint32_t)__cvta_generic_to_shared(p);
}

// Within an 8KB block: row = 64B (4 x 16B chunks), XOR-swizzled chunk position.
__device__ __forceinline__ uint32_t swz(int row, int chunk) {
    return (uint32_t)(row * 64 + ((chunk ^ ((row >> 1) & 3)) << 4));
}

#define MBAR_INIT(addr, cnt) \
    asm volatile("mbarrier.init.shared.b64 [%0], %1;" :: "r"(addr), "r"(cnt) : "memory")

#define MBAR_EXPECT_TX(addr, bytes) \
    asm volatile("mbarrier.arrive.expect_tx.shared.b64 _, [%0], %1;" \
                 :: "r"(addr), "r"(bytes) : "memory")

#define MBAR_ARRIVE(addr) \
    asm volatile("mbarrier.arrive.shared.b64 _, [%0];" :: "r"(addr) : "memory")

#define MB_WAIT(addr, ph) do { \
    uint32_t _d_; \
    asm volatile("{\n\t.reg .pred p;\n\t" \
        "mbarrier.try_wait.parity.acquire.cta.shared::cta.b64 p, [%1], %2;\n\t" \
        "selp.b32 %0, 1, 0, p;\n\t}" : "=r"(_d_) : "r"(addr), "r"(ph) : "memory"); \
    while (!_d_) { \
        asm volatile("{\n\t.reg .pred p;\n\t" \
            "mbarrier.try_wait.parity.acquire.cta.shared::cta.b64 p, [%1], %2, 0x989680;\n\t" \
            "selp.b32 %0, 1, 0, p;\n\t}" : "=r"(_d_) : "r"(addr), "r"(ph) : "memory"); \
    } \
} while (0)

__device__ __forceinline__ void bulk_cp(uint32_t dst, const void* src,
                                        uint32_t bytes, uint32_t mbar) {
    asm volatile(
        "cp.async.bulk.shared::cluster.global.mbarrier::complete_tx::bytes "
        "[%0], [%1], %2, [%3];"
        :: "r"(dst), "l"(src), "r"(bytes), "r"(mbar) : "memory");
}

__device__ __forceinline__ void ldsm_x4(uint32_t (&r)[4], uint32_t addr) {
    asm volatile("ldmatrix.sync.aligned.m8n8.x4.shared.b16 {%0,%1,%2,%3}, [%4];"
                 : "=r"(r[0]), "=r"(r[1]), "=r"(r[2]), "=r"(r[3]) : "r"(addr));
}

__device__ __forceinline__ void mma_bf16(float (&c)[4], const uint32_t (&a)[4],
                                         uint32_t b0, uint32_t b1) {
    asm volatile(
        "mma.sync.aligned.m16n8k16.row.col.f32.bf16.bf16.f32 "
        "{%0,%1,%2,%3}, {%4,%5,%6,%7}, {%8,%9}, {%0,%1,%2,%3};"
        : "+f"(c[0]), "+f"(c[1]), "+f"(c[2]), "+f"(c[3])
        : "r"(a[0]), "r"(a[1]), "r"(a[2]), "r"(a[3]), "r"(b0), "r"(b1));
}

// pack two floats into bf16x2 word: low half = lo, high half = hi
__device__ __forceinline__ uint32_t pack_bf16x2(float lo, float hi) {
    uint32_t r;
    asm("cvt.rn.bf16x2.f32 %0, %1, %2;" : "=r"(r) : "f"(hi), "f"(lo));
    return r;
}

// ---------------------------------------------------------------------------
// Kernel 1: MERGED prep. Blocks 0..8191: quantize+center activations.
// Blocks 8192..12287: center weights. Both write tiled+swizzled bf16 layout.
// ---------------------------------------------------------------------------
__global__ void prep_kernel(const float* __restrict__ x,
                            const float* __restrict__ act_scale,
                            const int* __restrict__ act_zp,
                            const int* __restrict__ wq,
                            const int* __restrict__ wzp)
{
    const int tid = threadIdx.x;
    const int kblk = tid >> 1;              // 0..127 (32-element blocks)
    const int g0 = (tid & 1) << 1;          // chunk pair within block: 0 or 2

    if (blockIdx.x < M_DIM) {
        // ---- activation quantization ----
        const int row = blockIdx.x;
        const int mtile = row >> 7, r = row & 127;
        const float s   = act_scale[0];
        const float zpf = (float)act_zp[0];
        const float4* xr = reinterpret_cast<const float4*>(
            x + (size_t)row * K_DIM + kblk * 32 + g0 * 8);

        size_t base = ((size_t)(mtile * 128 + kblk)) * SLAB_W;
        #pragma unroll
        for (int c = 0; c < 2; ++c) {       // two 16B chunks (8 bf16 each)
            float4 v0 = xr[c * 2 + 0];
            float4 v1 = xr[c * 2 + 1];
            float q[8] = {v0.x, v0.y, v0.z, v0.w, v1.x, v1.y, v1.z, v1.w};
            #pragma unroll
            for (int e = 0; e < 8; ++e)
                q[e] = fminf(fmaxf(rintf(__fdiv_rn(q[e], s)) + zpf, 0.f), 255.f) - zpf;
            uint4 w;
            w.x = pack_bf16x2(q[0], q[1]);
            w.y = pack_bf16x2(q[2], q[3]);
            w.z = pack_bf16x2(q[4], q[5]);
            w.w = pack_bf16x2(q[6], q[7]);
            int chunk = g0 + c;
            uint32_t woff = (uint32_t)(r * 16 + ((chunk ^ ((r >> 1) & 3)) << 2));
            *reinterpret_cast<uint4*>(&g_Ab[base + woff]) = w;
        }
    } else {
        // ---- weight centering ----
        const int row = blockIdx.x - M_DIM;
        const int ntile = row >> 7, r = row & 127;
        const float zw = (float)wzp[row];
        const int4* wr = reinterpret_cast<const int4*>(
            wq + (size_t)row * K_DIM + kblk * 32 + g0 * 8);

        size_t base = ((size_t)(ntile * 128 + kblk)) * SLAB_W;
        #pragma unroll
        for (int c = 0; c < 2; ++c) {
            int4 v0 = wr[c * 2 + 0];
            int4 v1 = wr[c * 2 + 1];
            float q[8] = {(float)v0.x, (float)v0.y, (float)v0.z, (float)v0.w,
                          (float)v1.x, (float)v1.y, (float)v1.z, (float)v1.w};
            #pragma unroll
            for (int e = 0; e < 8; ++e) q[e] -= zw;
            uint4 w;
            w.x = pack_bf16x2(q[0], q[1]);
            w.y = pack_bf16x2(q[2], q[3]);
            w.z = pack_bf16x2(q[4], q[5]);
            w.w = pack_bf16x2(q[6], q[7]);
            int chunk = g0 + c;
            uint32_t woff = (uint32_t)(r * 16 + ((chunk ^ ((r >> 1) & 3)) << 2));
            *reinterpret_cast<uint4*>(&g_Wb[base + woff]) = w;
        }
    }
}

// ---------------------------------------------------------------------------
// Kernel 2: bf16 HMMA GEMM, 128x128 CTA tile, 8 warps (4x2), warp tile 32x64.
// 6-stage ring, 8KB bulk copies, __syncthreads-free mainloop, cursor-based
// phase tracking (no dynamic-indexed arrays -> no local-mem traffic).
// ---------------------------------------------------------------------------
__global__ __launch_bounds__(256, 2)
void gemm_hmma_kernel(const float* __restrict__ wscale,
                      const float* __restrict__ ascale,
                      const float* __restrict__ bias,
                      float*       __restrict__ out)
{
    extern __shared__ __align__(1024) uint8_t smem_raw[];
    uint32_t raw = cvta_smem(smem_raw);
    uint32_t sbase = (raw + 1023u) & ~1023u;
    uint8_t* smem_gen = smem_raw + (sbase - raw);

    const int tid = threadIdx.x;
    const int wid = tid >> 5;
    const int lid = tid & 31;
    const int wm  = wid & 3;        // warp row (32 rows each)
    const int wn  = wid >> 2;       // warp col (64 cols each)
    const int tile_m = blockIdx.y << 7;
    const int tile_n = blockIdx.x << 7;

    const uint8_t* Abase = reinterpret_cast<const uint8_t*>(g_Ab)
                         + (size_t)blockIdx.y * 128 * SLAB;
    const uint8_t* Bbase = reinterpret_cast<const uint8_t*>(g_Wb)
                         + (size_t)blockIdx.x * 128 * SLAB;
    const uint32_t mbf = sbase + OFF_MBF;
    const uint32_t mbe = sbase + OFF_MBE;

    if (tid == 0) {
        #pragma unroll
        for (int s = 0; s < NST; ++s) {
            MBAR_INIT(mbf + s * 8, 1);
            MBAR_INIT(mbe + s * 8, 256);
        }
        asm volatile("fence.proxy.async.shared::cta;" ::: "memory");
    }

    // Epilogue constants
    float* tsc = reinterpret_cast<float*>(smem_gen + OFF_EPI);
    float* tbs = reinterpret_cast<float*>(smem_gen + OFF_EPI + 512);
    if (tid >= 128) {
        const float sa = ascale[0];
        int n = tid - 128;
        int o = tile_n + n;
        tsc[n] = sa * wscale[o];
        tbs[n] = bias[o];
    }
    __syncthreads();   // barriers initialized + constants visible

    // Producer cursor (tid 0 only): empty-barrier waits, initial phase 1 so
    // the first NST waits pass immediately. Register-only state.
    int p_stage = 0, p_phase = 1;

    // Prologue: fill NST-1 stages
    if (tid == 0) {
        #pragma unroll
        for (int s = 0; s < NST - 1; ++s) {
            MB_WAIT(mbe + p_stage * 8, p_phase);       // passes immediately
            MBAR_EXPECT_TX(mbf + p_stage * 8, 2 * SLAB);
            bulk_cp(sbase + OFF_A + p_stage * SLAB, Abase + (size_t)s * SLAB,
                    SLAB, mbf + p_stage * 8);
            bulk_cp(sbase + OFF_B + p_stage * SLAB, Bbase + (size_t)s * SLAB,
                    SLAB, mbf + p_stage * 8);
            if (++p_stage == NST) { p_stage = 0; p_phase ^= 1; }
        }
    }

    float acc[2][8][4];
    #pragma unroll
    for (int mt = 0; mt < 2; ++mt)
        #pragma unroll
        for (int nt = 0; nt < 8; ++nt)
            #pragma unroll
            for (int q = 0; q < 4; ++q) acc[mt][nt][q] = 0.f;

    // ldmatrix lane geometry (chunk = 16B = 8 bf16 = k8)
    const int a_row = (lid & 7) + ((lid >> 3) & 1) * 8;
    const int a_ch  = (lid >> 4);
    const int b_row = (lid & 7) + (lid >> 4) * 8;
    const int b_ch  = ((lid >> 3) & 1);

    // Consumer cursor: full-barrier waits, phase 0.
    int c_stage = 0, c_phase = 0;

    for (int it = 0; it < NIT; ++it) {
        MB_WAIT(mbf + c_stage * 8, c_phase);

        uint32_t aS = sbase + OFF_A + c_stage * SLAB;
        uint32_t bS = sbase + OFF_B + c_stage * SLAB;

        #pragma unroll
        for (int ks = 0; ks < 2; ++ks) {           // two k16 steps per slab
            const int cb = ks << 1;
            uint32_t a[2][4];
            #pragma unroll
            for (int mt = 0; mt < 2; ++mt)
                ldsm_x4(a[mt], aS + swz(wm * 32 + mt * 16 + a_row, cb + a_ch));
            uint32_t b[8][2];
            #pragma unroll
            for (int b4 = 0; b4 < 4; ++b4) {
                uint32_t r4[4];
                ldsm_x4(r4, bS + swz(wn * 64 + b4 * 16 + b_row, cb + b_ch));
                b[2*b4][0] = r4[0]; b[2*b4][1] = r4[1];
                b[2*b4+1][0] = r4[2]; b[2*b4+1][1] = r4[3];
            }
            #pragma unroll
            for (int mt = 0; mt < 2; ++mt)
                #pragma unroll
                for (int nt = 0; nt < 8; ++nt)
                    mma_bf16(acc[mt][nt], a[mt], b[nt][0], b[nt][1]);
        }

        // Done consuming this stage (ldmatrix results are in registers).
        MBAR_ARRIVE(mbe + c_stage * 8);
        if (++c_stage == NST) { c_stage = 0; c_phase ^= 1; }

        // Producer: refill the ring.
        int nx = it + NST - 1;
        if (tid == 0 && nx < NIT) {
            MB_WAIT(mbe + p_stage * 8, p_phase);       // backpressure
            MBAR_EXPECT_TX(mbf + p_stage * 8, 2 * SLAB);
            bulk_cp(sbase + OFF_A + p_stage * SLAB, Abase + (size_t)nx * SLAB,
                    SLAB, mbf + p_stage * 8);
            bulk_cp(sbase + OFF_B + p_stage * SLAB, Bbase + (size_t)nx * SLAB,
                    SLAB, mbf + p_stage * 8);
            if (++p_stage == NST) { p_stage = 0; p_phase ^= 1; }
        }
    }

    // ---------------- Epilogue: out = tsc[n]*acc + tbs[n] -------------------
    const int qrow = lid >> 2;
    const int qcol = (lid & 3) << 1;
    #pragma unroll
    for (int mt = 0; mt < 2; ++mt) {
        const int ml0 = wm * 32 + mt * 16 + qrow;
        float* orow0 = out + (size_t)(tile_m + ml0) * N_DIM + tile_n;
        float* orow1 = orow0 + (size_t)8 * N_DIM;
        #pragma unroll
        for (int nt = 0; nt < 8; ++nt) {
            const int nl = wn * 64 + nt * 8 + qcol;
            const float s0 = tsc[nl], s1 = tsc[nl + 1];
            const float g0 = tbs[nl], g1 = tbs[nl + 1];
            float2 v0, v1;
            v0.x = s0 * acc[mt][nt][0] + g0;
            v0.y = s1 * acc[mt][nt][1] + g1;
            v1.x = s0 * acc[mt][nt][2] + g0;
            v1.y = s1 * acc[mt][nt][3] + g1;
            *reinterpret_cast<float2*>(orow0 + nl) = v0;
            *reinterpret_cast<float2*>(orow1 + nl) = v1;
        }
    }
}

// ---------------------------------------------------------------------------
// Launch
// ---------------------------------------------------------------------------
extern "C" void kernel_launch(void* const* d_in, const int* in_sizes, int n_in,
                              void* d_out, int out_size)
{
    const float* x       = (const float*)d_in[0];
    const int*   wq      = (const int*)  d_in[1];
    const float* wscale  = (const float*)d_in[2];
    const int*   wzp     = (const int*)  d_in[3];
    const float* ascale  = (const float*)d_in[4];
    const int*   azp     = (const int*)  d_in[5];
    const float* bias    = (const float*)d_in[6];
    float*       out     = (float*)d_out;

    cudaFuncSetAttribute(gemm_hmma_kernel,
                         cudaFuncAttributeMaxDynamicSharedMemorySize, SMEM_BYTES);

    prep_kernel<<<M_DIM + N_DIM, 256>>>(x, ascale, azp, wq, wzp);

    dim3 grid(N_DIM / BN, M_DIM / BM);   // (32, 64)
    gemm_hmma_kernel<<<grid, 256, SMEM_BYTES>>>(wscale, ascale, bias, out);
}